// round 2
// baseline (speedup 1.0000x reference)
#include <cuda_runtime.h>
#include <cstdint>

#define NN   512
#define NMAT 8          // B*R = 2*4
#define TILE 64
#define CH   64         // c-chunk per smem stage
#define STR  66         // smem row stride (floats): 66*4=264B, 8B-aligned rows, 2-bank rotation

__device__ float  g_P[NMAT * NN * NN];   // packed masked probabilities, [m][row][col]
__device__ double g_T;                   // sum of min(p, x*y)
__device__ double g_SP;                  // sum of P

__device__ __forceinline__ float sigmoidf_(float x) {
    return 1.0f / (1.0f + __expf(-x));
}

__global__ void zero_kernel() { g_T = 0.0; g_SP = 0.0; }

// Pass 1: sigmoid + mask, transpose [B,N,N,R] -> 8 contiguous [N,N] matrices, sum P.
__global__ void __launch_bounds__(256) prep_kernel(const float* __restrict__ logits,
                                                   const int* __restrict__ mask) {
    int idx = blockIdx.x * 256 + threadIdx.x;      // over B*N*N = 524288 (exact fit)
    int b   = idx >> 18;
    int rem = idx & (NN * NN - 1);
    int a   = rem >> 9;
    int i   = rem & (NN - 1);

    float4 v = reinterpret_cast<const float4*>(logits)[idx];   // 4 relations packed
    float ma = (mask[b * NN + a] > 0) ? 1.0f : 0.0f;
    float mi = (mask[b * NN + i] > 0) ? 1.0f : 0.0f;
    float mm = ma * mi;

    float p0 = mm * sigmoidf_(v.x);
    float p1 = mm * sigmoidf_(v.y);
    float p2 = mm * sigmoidf_(v.z);
    float p3 = mm * sigmoidf_(v.w);

    int base = a * NN + i;
    int moff = b * 4 * NN * NN;
    g_P[moff + 0 * NN * NN + base] = p0;
    g_P[moff + 1 * NN * NN + base] = p1;
    g_P[moff + 2 * NN * NN + base] = p2;
    g_P[moff + 3 * NN * NN + base] = p3;

    float s = (p0 + p1) + (p2 + p3);
    #pragma unroll
    for (int o = 16; o; o >>= 1) s += __shfl_xor_sync(0xffffffffu, s, o);
    if ((threadIdx.x & 31) == 0) atomicAdd(&g_SP, (double)s);
}

// Pass 2: T = sum_{m,a,i,c} min(P[a,i], P[a,c]*P[i,c])
// Grid: 1024 blocks = m(8) * a-tile(8) * i-tile(8) * c-split(2). 256 threads.
// Thread (tx,ty) owns pairs a = a0+ty+16*ja, i = i0+tx+16*ji (4x4, strided for
// conflict-free LDS and coalesced p loads).
__global__ void __launch_bounds__(256, 2) trans_kernel() {
    __shared__ float Xs[TILE * STR];
    __shared__ float Ys[TILE * STR];

    int bid = blockIdx.x;
    int cs  = bid & 1;
    int ti  = (bid >> 1) & 7;
    int ta  = (bid >> 4) & 7;
    int m   = bid >> 7;

    const float* __restrict__ P = g_P + m * NN * NN;
    int a0 = ta * TILE, i0 = ti * TILE, c0 = cs * 256;

    int tid = threadIdx.x;
    int tx = tid & 15, ty = tid >> 4;

    // p block: 16 scalars per thread (coalesced across tx)
    float p[16];
    #pragma unroll
    for (int ja = 0; ja < 4; ++ja)
        #pragma unroll
        for (int ji = 0; ji < 4; ++ji)
            p[ja * 4 + ji] = P[(a0 + ty + 16 * ja) * NN + (i0 + tx + 16 * ji)];

    unsigned long long acc[16];
    #pragma unroll
    for (int k = 0; k < 16; ++k) acc[k] = 0ull;   // f32x2 {0,0}

    for (int ch = 0; ch < 256; ch += CH) {
        int cb = c0 + ch;
        if (ch) __syncthreads();
        // Stage X (rows a0..) and Y (rows i0..) tiles: 64 rows x 64 c each.
        #pragma unroll
        for (int r = 0; r < 4; ++r) {
            int fi  = r * 256 + tid;      // float4 index 0..1023
            int row = fi >> 4;            // 16 float4 per row
            int c4  = fi & 15;
            float4 vx = *reinterpret_cast<const float4*>(&P[(a0 + row) * NN + cb + c4 * 4]);
            float4 vy = *reinterpret_cast<const float4*>(&P[(i0 + row) * NN + cb + c4 * 4]);
            float* dx = &Xs[row * STR + c4 * 4];
            float* dy = &Ys[row * STR + c4 * 4];
            reinterpret_cast<float2*>(dx)[0] = make_float2(vx.x, vx.y);
            reinterpret_cast<float2*>(dx)[1] = make_float2(vx.z, vx.w);
            reinterpret_cast<float2*>(dy)[0] = make_float2(vy.x, vy.y);
            reinterpret_cast<float2*>(dy)[1] = make_float2(vy.z, vy.w);
        }
        __syncthreads();

        #pragma unroll 4
        for (int cc = 0; cc < CH / 2; ++cc) {
            unsigned long long x2[4], y2[4];
            #pragma unroll
            for (int j = 0; j < 4; ++j)
                x2[j] = *reinterpret_cast<const unsigned long long*>(
                            &Xs[(ty + 16 * j) * STR + 2 * cc]);
            #pragma unroll
            for (int j = 0; j < 4; ++j)
                y2[j] = *reinterpret_cast<const unsigned long long*>(
                            &Ys[(tx + 16 * j) * STR + 2 * cc]);
            #pragma unroll
            for (int ja = 0; ja < 4; ++ja)
                #pragma unroll
                for (int ji = 0; ji < 4; ++ji) {
                    int k = ja * 4 + ji;
                    unsigned long long q;
                    asm("mul.rn.f32x2 %0, %1, %2;"
                        : "=l"(q) : "l"(x2[ja]), "l"(y2[ji]));
                    asm("{\n\t"
                        ".reg .f32 l, h;\n\t"
                        "mov.b64 {l, h}, %1;\n\t"
                        "min.f32 l, l, %2;\n\t"
                        "min.f32 h, h, %2;\n\t"
                        "mov.b64 %0, {l, h};\n\t"
                        "}"
                        : "=l"(q) : "l"(q), "f"(p[k]));
                    asm("add.rn.f32x2 %0, %1, %2;"
                        : "=l"(acc[k]) : "l"(acc[k]), "l"(q));
                }
        }
    }

    float s = 0.0f;
    #pragma unroll
    for (int k = 0; k < 16; ++k) {
        float2 f = *reinterpret_cast<float2*>(&acc[k]);
        s += f.x + f.y;
    }
    #pragma unroll
    for (int o = 16; o; o >>= 1) s += __shfl_xor_sync(0xffffffffu, s, o);
    if ((tid & 31) == 0) atomicAdd(&g_T, (double)s);
}

// result = (N * sumP - T) / (R*B)
__global__ void finalize_kernel(float* __restrict__ out) {
    out[0] = (float)(((double)NN * g_SP - g_T) * 0.125);
}

extern "C" void kernel_launch(void* const* d_in, const int* in_sizes, int n_in,
                              void* d_out, int out_size) {
    const float* logits = (const float*)d_in[0];   // [2,512,512,4] fp32
    const int*   masks  = (const int*)d_in[1];     // [2,512] int32
    (void)in_sizes; (void)n_in; (void)out_size;

    zero_kernel<<<1, 1>>>();
    prep_kernel<<<(2 * NN * NN) / 256, 256>>>(logits, masks);   // 2048 blocks
    trans_kernel<<<NMAT * 8 * 8 * 2, 256>>>();                  // 1024 blocks
    finalize_kernel<<<1, 1>>>((float*)d_out);
}

// round 5
// speedup vs baseline: 1.1699x; 1.1699x over previous
#include <cuda_runtime.h>
#include <cstdint>

#define NN     512
#define NMAT   8          // B*R = 2*4
#define TILE   64
#define CH     64         // c-chunk per smem stage
#define STR    66         // smem row stride (floats): conflict-free LDS.64
#define NUNITS 1024       // m(8) * ta(8) * ti(8) * cs(2)
#define GRID   296        // 148 SMs * 2 resident blocks

__device__ float    g_P[NMAT * NN * NN];  // packed masked probabilities [m][row][col]
__device__ double   g_acc;                // sum over units of (512*sum_p [cs0] - sum_min)
__device__ unsigned g_unit;               // dynamic work counter
__device__ unsigned g_done;               // finished-block counter

__device__ __forceinline__ float sigmoidf_(float x) {
    return 1.0f / (1.0f + __expf(-x));
}

// Pass 1: sigmoid + mask, transpose [B,N,N,R] -> 8 contiguous [N,N] matrices.
__global__ void __launch_bounds__(256) prep_kernel(const float* __restrict__ logits,
                                                   const int* __restrict__ mask) {
    int idx = blockIdx.x * 256 + threadIdx.x;      // over B*N*N = 524288 (exact fit)
    int b   = idx >> 18;
    int rem = idx & (NN * NN - 1);
    int a   = rem >> 9;
    int i   = rem & (NN - 1);

    float4 v = reinterpret_cast<const float4*>(logits)[idx];   // 4 relations packed
    float mm = ((mask[b * NN + a] > 0) && (mask[b * NN + i] > 0)) ? 1.0f : 0.0f;

    int base = a * NN + i;
    int moff = b * 4 * NN * NN;
    g_P[moff + 0 * NN * NN + base] = mm * sigmoidf_(v.x);
    g_P[moff + 1 * NN * NN + base] = mm * sigmoidf_(v.y);
    g_P[moff + 2 * NN * NN + base] = mm * sigmoidf_(v.z);
    g_P[moff + 3 * NN * NN + base] = mm * sigmoidf_(v.w);
}

// Pass 2 (persistent, dynamic units, fused finalize):
// unit = (m, a-tile, i-tile, c-half). Per unit: 64x64 pairs x 256 c's.
// s_unit = (cs==0 ? 512*sum(p) : 0) - sum_{a,i,c} min(p_ai, P[a,c]*P[i,c])
// out = sum(s_unit) / 8. Last block writes out and resets counters for replay.
__global__ void __launch_bounds__(256, 2) trans_kernel(float* __restrict__ out) {
    __shared__ float Xs[TILE * STR];
    __shared__ float Ys[TILE * STR];
    __shared__ unsigned s_u;
    __shared__ double  red[8];

    int tid = threadIdx.x;
    int tx = tid & 15, ty = tid >> 4;

    double local = 0.0;

    for (;;) {
        __syncthreads();                    // protect s_u / smem from previous unit
        if (tid == 0) s_u = atomicAdd(&g_unit, 1u);
        __syncthreads();
        unsigned u = s_u;
        if (u >= NUNITS) break;

        int cs = u & 1;
        int ti = (u >> 1) & 7;
        int ta = (u >> 4) & 7;
        int m  = u >> 7;

        const float* __restrict__ P = g_P + m * NN * NN;
        int a0 = ta * TILE, i0 = ti * TILE, c0 = cs * 256;

        // p block: 16 scalars per thread (strided 4x4, coalesced across tx)
        float p[16];
        #pragma unroll
        for (int ja = 0; ja < 4; ++ja)
            #pragma unroll
            for (int ji = 0; ji < 4; ++ji)
                p[ja * 4 + ji] = P[(a0 + ty + 16 * ja) * NN + (i0 + tx + 16 * ji)];

        if (cs == 0) {
            float ps = 0.0f;
            #pragma unroll
            for (int k = 0; k < 16; ++k) ps += p[k];
            local += 512.0 * (double)ps;
        }

        unsigned long long acc[16];
        #pragma unroll
        for (int k = 0; k < 16; ++k) acc[k] = 0ull;   // f32x2 {0,0}

        for (int ch = 0; ch < 256; ch += CH) {
            int cb = c0 + ch;
            // Stage X (rows a0..) and Y (rows i0..): 64 rows x 64 c each.
            #pragma unroll
            for (int r = 0; r < 4; ++r) {
                int fi  = r * 256 + tid;      // float4 index 0..1023
                int row = fi >> 4;            // 16 float4 per row
                int c4  = fi & 15;
                float4 vx = *reinterpret_cast<const float4*>(&P[(a0 + row) * NN + cb + c4 * 4]);
                float4 vy = *reinterpret_cast<const float4*>(&P[(i0 + row) * NN + cb + c4 * 4]);
                float* dx = &Xs[row * STR + c4 * 4];
                float* dy = &Ys[row * STR + c4 * 4];
                reinterpret_cast<float2*>(dx)[0] = make_float2(vx.x, vx.y);
                reinterpret_cast<float2*>(dx)[1] = make_float2(vx.z, vx.w);
                reinterpret_cast<float2*>(dy)[0] = make_float2(vy.x, vy.y);
                reinterpret_cast<float2*>(dy)[1] = make_float2(vy.z, vy.w);
            }
            __syncthreads();

            #pragma unroll 4
            for (int cc = 0; cc < CH / 2; ++cc) {
                unsigned long long x2[4], y2[4];
                #pragma unroll
                for (int j = 0; j < 4; ++j)
                    x2[j] = *reinterpret_cast<const unsigned long long*>(
                                &Xs[(ty + 16 * j) * STR + 2 * cc]);
                #pragma unroll
                for (int j = 0; j < 4; ++j)
                    y2[j] = *reinterpret_cast<const unsigned long long*>(
                                &Ys[(tx + 16 * j) * STR + 2 * cc]);
                #pragma unroll
                for (int ja = 0; ja < 4; ++ja)
                    #pragma unroll
                    for (int ji = 0; ji < 4; ++ji) {
                        int k = ja * 4 + ji;
                        unsigned long long q;
                        asm("mul.rn.f32x2 %0, %1, %2;"
                            : "=l"(q) : "l"(x2[ja]), "l"(y2[ji]));
                        asm("{\n\t"
                            ".reg .f32 l, h;\n\t"
                            "mov.b64 {l, h}, %1;\n\t"
                            "min.f32 l, l, %2;\n\t"
                            "min.f32 h, h, %2;\n\t"
                            "mov.b64 %0, {l, h};\n\t"
                            "}"
                            : "=l"(q) : "l"(q), "f"(p[k]));
                        asm("add.rn.f32x2 %0, %1, %2;"
                            : "=l"(acc[k]) : "l"(acc[k]), "l"(q));
                    }
            }
            __syncthreads();
        }

        float s = 0.0f;
        #pragma unroll
        for (int k = 0; k < 16; ++k) {
            float2 f = *reinterpret_cast<float2*>(&acc[k]);
            s += f.x + f.y;
        }
        local -= (double)s;
    }

    // Block reduction of per-thread doubles, then one atomicAdd per block.
    #pragma unroll
    for (int o = 16; o; o >>= 1) local += __shfl_xor_sync(0xffffffffu, local, o);
    if ((tid & 31) == 0) red[tid >> 5] = local;
    __syncthreads();
    if (tid < 32) {
        double bsum = (tid < 8) ? red[tid] : 0.0;
        #pragma unroll
        for (int o = 4; o; o >>= 1) bsum += __shfl_xor_sync(0xffffffffu, bsum, o);
        if (tid == 0) {
            atomicAdd(&g_acc, bsum);
            __threadfence();
            unsigned d = atomicAdd(&g_done, 1u);
            if (d == GRID - 1) {               // last block: finalize + reset for replay
                out[0] = (float)(g_acc * 0.125);
                g_acc  = 0.0;
                g_done = 0u;
                g_unit = 0u;
            }
        }
    }
}

extern "C" void kernel_launch(void* const* d_in, const int* in_sizes, int n_in,
                              void* d_out, int out_size) {
    const float* logits = (const float*)d_in[0];   // [2,512,512,4] fp32
    const int*   masks  = (const int*)d_in[1];     // [2,512] int32
    (void)in_sizes; (void)n_in; (void)out_size;

    prep_kernel<<<(2 * NN * NN) / 256, 256>>>(logits, masks);   // 2048 blocks
    trans_kernel<<<GRID, 256>>>((float*)d_out);                 // persistent
}

// round 6
// speedup vs baseline: 1.1897x; 1.0169x over previous
#include <cuda_runtime.h>
#include <cstdint>

#define NN     512
#define NMAT   8          // B*R = 2*4
#define TILE   64
#define CH     32         // c-chunk per smem stage
#define NSTG   8          // 256 c's per unit / CH
#define STR    34         // smem row stride (floats): 136B rows, 8B-aligned, bank step 2
#define NUNITS 1024       // m(8) * ta(8) * ti(8) * cs(2)
#define GRID   296        // 148 SMs * 2 resident blocks

__device__ float    g_P[NMAT * NN * NN];  // packed masked probabilities [m][row][col]
__device__ double   g_acc;                // sum over units of (512*sum_p [cs0] - sum_min)
__device__ unsigned g_unit;               // dynamic work counter
__device__ unsigned g_done;               // finished-block counter

__device__ __forceinline__ float sigmoidf_(float x) {
    return 1.0f / (1.0f + __expf(-x));
}

// Pass 1: sigmoid + mask, transpose [B,N,N,R] -> 8 contiguous [N,N] matrices.
__global__ void __launch_bounds__(256) prep_kernel(const float* __restrict__ logits,
                                                   const int* __restrict__ mask) {
    int idx = blockIdx.x * 256 + threadIdx.x;      // over B*N*N = 524288 (exact fit)
    int b   = idx >> 18;
    int rem = idx & (NN * NN - 1);
    int a   = rem >> 9;
    int i   = rem & (NN - 1);

    float4 v = reinterpret_cast<const float4*>(logits)[idx];   // 4 relations packed
    float mm = ((mask[b * NN + a] > 0) && (mask[b * NN + i] > 0)) ? 1.0f : 0.0f;

    int base = a * NN + i;
    int moff = b * 4 * NN * NN;
    g_P[moff + 0 * NN * NN + base] = mm * sigmoidf_(v.x);
    g_P[moff + 1 * NN * NN + base] = mm * sigmoidf_(v.y);
    g_P[moff + 2 * NN * NN + base] = mm * sigmoidf_(v.z);
    g_P[moff + 3 * NN * NN + base] = mm * sigmoidf_(v.w);
}

// Stage one CH-wide slab of X (rows a0..) and Y (rows i0..) via cp.async (8B).
// 64 rows x 32 c = 16 8B-chunks per row; 4 chunks per thread per array.
__device__ __forceinline__ void stage_cp(const float* __restrict__ P,
                                         int a0, int i0, int cb,
                                         float* Xb, float* Yb, int tid) {
    #pragma unroll
    for (int k = 0; k < 4; ++k) {
        int idx = k * 256 + tid;
        int row = idx >> 4;
        int ch8 = idx & 15;
        const float* sx = P + (a0 + row) * NN + cb + ch8 * 2;
        const float* sy = P + (i0 + row) * NN + cb + ch8 * 2;
        unsigned dx = (unsigned)__cvta_generic_to_shared(Xb + row * STR + ch8 * 2);
        unsigned dy = (unsigned)__cvta_generic_to_shared(Yb + row * STR + ch8 * 2);
        asm volatile("cp.async.ca.shared.global [%0], [%1], 8;\n\t"
                     "cp.async.ca.shared.global [%2], [%3], 8;"
                     :: "r"(dx), "l"(sx), "r"(dy), "l"(sy));
    }
    asm volatile("cp.async.commit_group;");
}

// Pass 2 (persistent, dynamic units, cp.async double-buffered, fused finalize):
// unit = (m, a-tile, i-tile, c-half). Per unit: 64x64 pairs x 256 c's.
// s_unit = (cs==0 ? 512*sum(p) : 0) - sum_{a,i,c} min(p_ai, P[a,c]*P[i,c])
__global__ void __launch_bounds__(256, 2) trans_kernel(float* __restrict__ out) {
    __shared__ float Xs[2][TILE * STR];
    __shared__ float Ys[2][TILE * STR];
    __shared__ unsigned s_u;
    __shared__ double  red[8];

    int tid = threadIdx.x;
    int tx = tid & 15, ty = tid >> 4;

    double local = 0.0;

    for (;;) {
        __syncthreads();                    // protect s_u / smem from previous unit
        if (tid == 0) s_u = atomicAdd(&g_unit, 1u);
        __syncthreads();
        unsigned u = s_u;
        if (u >= NUNITS) break;

        int cs = u & 1;
        int ti = (u >> 1) & 7;
        int ta = (u >> 4) & 7;
        int m  = u >> 7;

        const float* __restrict__ P = g_P + m * NN * NN;
        int a0 = ta * TILE, i0 = ti * TILE, c0 = cs * 256;

        // Kick off stage 0 immediately; p-loads below overlap with it.
        stage_cp(P, a0, i0, c0, Xs[0], Ys[0], tid);

        // p block: 16 scalars per thread (strided 4x4, coalesced across tx)
        float p[16];
        #pragma unroll
        for (int ja = 0; ja < 4; ++ja)
            #pragma unroll
            for (int ji = 0; ji < 4; ++ji)
                p[ja * 4 + ji] = P[(a0 + ty + 16 * ja) * NN + (i0 + tx + 16 * ji)];

        if (cs == 0) {
            float ps = 0.0f;
            #pragma unroll
            for (int k = 0; k < 16; ++k) ps += p[k];
            local += 512.0 * (double)ps;
        }

        unsigned long long acc[16];
        #pragma unroll
        for (int k = 0; k < 16; ++k) acc[k] = 0ull;   // f32x2 {0,0}

        for (int s = 0; s < NSTG; ++s) {
            asm volatile("cp.async.wait_group 0;" ::: "memory");
            __syncthreads();               // stage s visible; buf[(s+1)&1] free
            if (s < NSTG - 1)
                stage_cp(P, a0, i0, c0 + (s + 1) * CH, Xs[(s + 1) & 1], Ys[(s + 1) & 1], tid);

            const float* Xb = Xs[s & 1];
            const float* Yb = Ys[s & 1];
            #pragma unroll 4
            for (int cc = 0; cc < CH / 2; ++cc) {
                unsigned long long x2[4], y2[4];
                #pragma unroll
                for (int j = 0; j < 4; ++j)
                    x2[j] = *reinterpret_cast<const unsigned long long*>(
                                &Xb[(ty + 16 * j) * STR + 2 * cc]);
                #pragma unroll
                for (int j = 0; j < 4; ++j)
                    y2[j] = *reinterpret_cast<const unsigned long long*>(
                                &Yb[(tx + 16 * j) * STR + 2 * cc]);
                #pragma unroll
                for (int ja = 0; ja < 4; ++ja)
                    #pragma unroll
                    for (int ji = 0; ji < 4; ++ji) {
                        int k = ja * 4 + ji;
                        unsigned long long q;
                        asm("mul.rn.f32x2 %0, %1, %2;"
                            : "=l"(q) : "l"(x2[ja]), "l"(y2[ji]));
                        asm("{\n\t"
                            ".reg .f32 l, h;\n\t"
                            "mov.b64 {l, h}, %1;\n\t"
                            "min.f32 l, l, %2;\n\t"
                            "min.f32 h, h, %2;\n\t"
                            "mov.b64 %0, {l, h};\n\t"
                            "}"
                            : "=l"(q) : "l"(q), "f"(p[k]));
                        asm("add.rn.f32x2 %0, %1, %2;"
                            : "=l"(acc[k]) : "l"(acc[k]), "l"(q));
                    }
            }
        }

        float s = 0.0f;
        #pragma unroll
        for (int k = 0; k < 16; ++k) {
            float2 f = *reinterpret_cast<float2*>(&acc[k]);
            s += f.x + f.y;
        }
        local -= (double)s;
    }

    // Block reduction of per-thread doubles, then one atomicAdd per block.
    #pragma unroll
    for (int o = 16; o; o >>= 1) local += __shfl_xor_sync(0xffffffffu, local, o);
    if ((tid & 31) == 0) red[tid >> 5] = local;
    __syncthreads();
    if (tid < 32) {
        double bsum = (tid < 8) ? red[tid] : 0.0;
        #pragma unroll
        for (int o = 4; o; o >>= 1) bsum += __shfl_xor_sync(0xffffffffu, bsum, o);
        if (tid == 0) {
            atomicAdd(&g_acc, bsum);
            __threadfence();
            unsigned d = atomicAdd(&g_done, 1u);
            if (d == GRID - 1) {               // last block: finalize + reset for replay
                out[0] = (float)(g_acc * 0.125);
                g_acc  = 0.0;
                g_done = 0u;
                g_unit = 0u;
            }
        }
    }
}

extern "C" void kernel_launch(void* const* d_in, const int* in_sizes, int n_in,
                              void* d_out, int out_size) {
    const float* logits = (const float*)d_in[0];   // [2,512,512,4] fp32
    const int*   masks  = (const int*)d_in[1];     // [2,512] int32
    (void)in_sizes; (void)n_in; (void)out_size;

    prep_kernel<<<(2 * NN * NN) / 256, 256>>>(logits, masks);   // 2048 blocks
    trans_kernel<<<GRID, 256>>>((float*)d_out);                 // persistent
}